// round 16
// baseline (speedup 1.0000x reference)
#include <cuda_runtime.h>
#include <cuda_bf16.h>
#include <cuda_fp16.h>
#include <math.h>
#include <stdint.h>

#define B_   2
#define S_   2048
#define NH_  16
#define NKV_ 8
#define HD_  128
#define MROWS (B_ * S_)          // 4096

// ---------------- scratch (device globals; no allocation allowed) ----------
__device__ float g_cos[S_ * 64];
__device__ float g_sin[S_ * 64];
// pre-converted fp16 copies (hidden + weights: hi only)
__device__ __half g_hid_h[(size_t)MROWS * 1024];
__device__ __half g_wq_h[(size_t)1024 * 2048];
__device__ __half g_wk_h[(size_t)1024 * 1024];
__device__ __half g_wv_h[(size_t)1024 * 1024];
__device__ __half g_wo_h[(size_t)2048 * 1024];
// attention output (hi only)
__device__ __half g_at_h[(size_t)MROWS * 2048];
// fp16 q/k/v for attention (q pre-scaled; RMSNorm+RoPE applied in QKV epilogue)
__device__ __half g_qh[(size_t)B_ * S_ * NH_ * HD_];
__device__ __half g_kh[(size_t)B_ * S_ * NKV_ * HD_];
__device__ __half g_vh[(size_t)B_ * S_ * NKV_ * HD_];

// ---------------- helpers ---------------------------------------------------
__device__ __forceinline__ uint32_t smem_u32(const void* p) {
    uint32_t a;
    asm("{ .reg .u64 t; cvta.to.shared.u64 t, %1; cvt.u32.u64 %0, t; }"
        : "=r"(a) : "l"(p));
    return a;
}
__device__ __forceinline__ void ldsm4(uint32_t* r, uint32_t addr) {
    asm volatile("ldmatrix.sync.aligned.m8n8.x4.shared.b16 {%0,%1,%2,%3}, [%4];"
                 : "=r"(r[0]), "=r"(r[1]), "=r"(r[2]), "=r"(r[3]) : "r"(addr));
}
__device__ __forceinline__ void ldsm4t(uint32_t* r, uint32_t addr) {
    asm volatile("ldmatrix.sync.aligned.m8n8.x4.trans.shared.b16 {%0,%1,%2,%3}, [%4];"
                 : "=r"(r[0]), "=r"(r[1]), "=r"(r[2]), "=r"(r[3]) : "r"(addr));
}
// fp16 mma, f32 accum
__device__ __forceinline__ void mma16816h(float* c, const uint32_t* a,
                                          uint32_t b0, uint32_t b1) {
    asm volatile(
        "mma.sync.aligned.m16n8k16.row.col.f32.f16.f16.f32 "
        "{%0,%1,%2,%3}, {%4,%5,%6,%7}, {%8,%9}, {%0,%1,%2,%3};"
        : "+f"(c[0]), "+f"(c[1]), "+f"(c[2]), "+f"(c[3])
        : "r"(a[0]), "r"(a[1]), "r"(a[2]), "r"(a[3]), "r"(b0), "r"(b1));
}
__device__ __forceinline__ uint32_t cvt2h(float a, float b) {
    __half2 h = __floats2half2_rn(a, b);
    return *(uint32_t*)&h;
}
// fast 2^y on the FMA pipe (no MUFU)
__device__ __forceinline__ float exp2fast(float y) {
    y = fmaxf(y, -126.0f);
    float r = y + 12582912.0f;
    float kf = r - 12582912.0f;
    float f = y - kf;
    float p = 1.3333558146e-3f;
    p = fmaf(p, f, 9.6181291076e-3f);
    p = fmaf(p, f, 5.5504108664e-2f);
    p = fmaf(p, f, 2.4022650696e-1f);
    p = fmaf(p, f, 6.9314718056e-1f);
    p = fmaf(p, f, 1.0f);
    return __int_as_float(__float_as_int(p) + (__float_as_int(r) << 23));
}

#define CP_ASYNC16(dst, src) \
    asm volatile("cp.async.cg.shared.global [%0], [%1], 16;" \
                 :: "r"(dst), "l"(src))
#define CP_COMMIT() asm volatile("cp.async.commit_group;" ::: "memory")
#define CP_WAIT1()  asm volatile("cp.async.wait_group 1;" ::: "memory")
#define CP_WAIT0()  asm volatile("cp.async.wait_group 0;" ::: "memory")

// ============================================================================
// ONE conversion kernel: fp32 -> fp16 hi for hidden + all four weights.
// ============================================================================
__global__ void convert_all_kernel(const float* __restrict__ hid,
                                   const float* __restrict__ Wq,
                                   const float* __restrict__ Wk,
                                   const float* __restrict__ Wv,
                                   const float* __restrict__ Wo,
                                   __half* __restrict__ hidh,
                                   __half* __restrict__ wqh,
                                   __half* __restrict__ wkh,
                                   __half* __restrict__ wvh,
                                   __half* __restrict__ woh) {
    int idx = blockIdx.x * blockDim.x + threadIdx.x;
    const int NH8 = MROWS * 1024 / 8;   // 524288
    const int NQ  = 1024 * 2048 / 8;    // 262144
    const int NK  = 1024 * 1024 / 8;    // 131072
    const float* in;
    __half* outp;
    int li;
    if (idx < NH8)                        { in = hid; outp = hidh; li = idx; }
    else if (idx < NH8 + NQ)              { in = Wq; outp = wqh; li = idx - NH8; }
    else if (idx < NH8 + NQ + NK)         { in = Wk; outp = wkh; li = idx - NH8 - NQ; }
    else if (idx < NH8 + NQ + 2 * NK)     { in = Wv; outp = wvh; li = idx - NH8 - NQ - NK; }
    else if (idx < NH8 + 2 * NQ + 2 * NK) { in = Wo; outp = woh; li = idx - NH8 - NQ - 2 * NK; }
    else return;
    const float4 x0 = ((const float4*)in)[2 * li];
    const float4 x1 = ((const float4*)in)[2 * li + 1];
    uint4 h;
    h.x = cvt2h(x0.x, x0.y);
    h.y = cvt2h(x0.z, x0.w);
    h.z = cvt2h(x1.x, x1.y);
    h.w = cvt2h(x1.z, x1.w);
    ((uint4*)outp)[li] = h;
}

// ============================================================================
// GEMM mainloop macro body (1-term fp16, KC=32, 3-stage cp.async; proven).
// Produces acc[4][4][4]; assumes tid/lane/wid/wm/wn/a_row/a_off/b_kr/b_off.
// ============================================================================
#define STG_SZ 18944u

#define GEMM_MAINLOOP(AHP, BHP, M0, N0, NN, KK, SBASE)                         \
    {                                                                          \
        const int nch = (KK) >> 5;                                             \
        _Pragma("unroll")                                                      \
        for (int c = 0; c < 2; c++) {                                          \
            const uint32_t st = (SBASE) + (uint32_t)c * STG_SZ;                \
            const __half* ah = (AHP) + (size_t)((M0) + a_row) * (KK) + c * 32 + a_off; \
            uint32_t da = st + (uint32_t)(a_row * 80 + a_off * 2);             \
            CP_ASYNC16(da, ah);                                                \
            CP_ASYNC16(da + 16, ah + 8);                                       \
            const __half* bh = (BHP) + (size_t)(c * 32 + b_kr) * (NN) + (N0) + b_off; \
            uint32_t db = st + 10240u + (uint32_t)(b_kr * 272 + b_off * 2);    \
            CP_ASYNC16(db, bh);                                                \
            CP_ASYNC16(db + 16, bh + 8);                                       \
            CP_COMMIT();                                                       \
        }                                                                      \
        for (int c = 0; c < nch; c++) {                                        \
            CP_WAIT1();                                                        \
            __syncthreads();                                                   \
            const uint32_t st = (SBASE) + (uint32_t)(c % 3) * STG_SZ;          \
            _Pragma("unroll")                                                  \
            for (int ks = 0; ks < 2; ks++) {                                   \
                uint32_t ah[4][4], bh[2][4];                                   \
                const uint32_t aoff =                                          \
                    st + (uint32_t)((wm + (lane & 15)) * 80 +                  \
                                    (ks * 16 + ((lane >> 4) << 3)) * 2);       \
                _Pragma("unroll")                                              \
                for (int mt = 0; mt < 4; mt++)                                 \
                    ldsm4(ah[mt], aoff + mt * 16 * 80);                        \
                const uint32_t bbase =                                         \
                    st + 10240u + (uint32_t)((ks * 16 + (lane & 15)) * 272 +   \
                                             (wn + ((lane >> 4) << 3)) * 2);   \
                _Pragma("unroll")                                              \
                for (int ng = 0; ng < 2; ng++)                                 \
                    ldsm4t(bh[ng], bbase + ng * 32);                           \
                _Pragma("unroll")                                              \
                for (int mt = 0; mt < 4; mt++)                                 \
                    _Pragma("unroll")                                          \
                    for (int nt = 0; nt < 4; nt++) {                           \
                        const int ng = nt >> 1;                                \
                        const int hf = (nt & 1) * 2;                           \
                        mma16816h(acc[mt][nt], ah[mt], bh[ng][hf], bh[ng][hf + 1]); \
                    }                                                          \
            }                                                                  \
            __syncthreads();                                                   \
            const int nc = c + 2;                                              \
            if (nc < nch) {                                                    \
                const uint32_t st2 = (SBASE) + (uint32_t)(nc % 3) * STG_SZ;    \
                const __half* ahp = (AHP) + (size_t)((M0) + a_row) * (KK) + nc * 32 + a_off; \
                uint32_t da = st2 + (uint32_t)(a_row * 80 + a_off * 2);        \
                CP_ASYNC16(da, ahp);                                           \
                CP_ASYNC16(da + 16, ahp + 8);                                  \
                const __half* bhp = (BHP) + (size_t)(nc * 32 + b_kr) * (NN) + (N0) + b_off; \
                uint32_t db = st2 + 10240u + (uint32_t)(b_kr * 272 + b_off * 2); \
                CP_ASYNC16(db, bhp);                                           \
                CP_ASYNC16(db + 16, bhp + 8);                                  \
            }                                                                  \
            CP_COMMIT();                                                       \
        }                                                                      \
    }

// ============================================================================
// Fused QKV GEMM + RMSNorm + RoPE + fp16 store.
// blockIdx.x spans [Wq 2048 | Wk 1024 | Wv 1024]; each 128-col tile = 1 head.
// ============================================================================
__global__ __launch_bounds__(256, 2)
void qkv_gemm_kernel(const __half* __restrict__ Ah,
                     const __half* __restrict__ Wq,
                     const __half* __restrict__ Wk,
                     const __half* __restrict__ Wv,
                     const float* __restrict__ qw,
                     const float* __restrict__ kw,
                     const float* __restrict__ ctab,
                     const float* __restrict__ stab,
                     __half* __restrict__ qh, __half* __restrict__ kh,
                     __half* __restrict__ vh) {
    extern __shared__ __align__(16) char dsm[];
    const uint32_t sbase = smem_u32(dsm);

    const int n0g = blockIdx.x * 128;
    const __half* Bh;
    __half* outp;
    const float* w;
    int N, n0, nheads, seg;
    if (n0g < 2048)      { Bh = Wq; outp = qh; w = qw; N = 2048; n0 = n0g;        nheads = 16; seg = 0; }
    else if (n0g < 3072) { Bh = Wk; outp = kh; w = kw; N = 1024; n0 = n0g - 2048; nheads = 8;  seg = 1; }
    else                 { Bh = Wv; outp = vh; w = kw; N = 1024; n0 = n0g - 3072; nheads = 8;  seg = 2; }

    const int tid  = threadIdx.x;
    const int lane = tid & 31;
    const int wid  = tid >> 5;
    const int wm = (wid >> 2) * 64;
    const int wn = (wid & 3) * 32;
    const int m0 = blockIdx.y * 128;

    float acc[4][4][4];
#pragma unroll
    for (int i = 0; i < 4; i++)
#pragma unroll
        for (int j = 0; j < 4; j++)
#pragma unroll
            for (int r = 0; r < 4; r++) acc[i][j][r] = 0.0f;

    const int a_row = tid >> 1;
    const int a_off = (tid & 1) * 16;
    const int b_kr  = tid >> 3;
    const int b_off = (tid & 7) * 16;

    GEMM_MAINLOOP(Ah, Bh, m0, n0, N, 1024, sbase);

    // ---- epilogue ----
    const int h  = n0 >> 7;
    const int bb = m0 >> 11;   // batch (128 | 2048 => tile within one batch)
    const int sbase_row = m0 & 2047;

    if (seg == 2) {
        // V: plain fp16 convert + strided store
#pragma unroll
        for (int mt = 0; mt < 4; mt++) {
            const int r0 = wm + mt * 16 + (lane >> 2);
            const int s0 = sbase_row + r0;
            const size_t o0 = ((size_t)(bb * S_ + s0) * nheads + h) * HD_;
            const size_t o1 = ((size_t)(bb * S_ + s0 + 8) * nheads + h) * HD_;
#pragma unroll
            for (int nt = 0; nt < 4; nt++) {
                const int c = wn + nt * 8 + (lane & 3) * 2;
                *(uint32_t*)&outp[o0 + c] = cvt2h(acc[mt][nt][0], acc[mt][nt][1]);
                *(uint32_t*)&outp[o1 + c] = cvt2h(acc[mt][nt][2], acc[mt][nt][3]);
            }
        }
        return;
    }

    // Q/K: RMSNorm + RoPE
    // 1) per-row sum of squares (warp covers 32 cols; reduce over lane&3)
    float ssa[4], ssb[4];
#pragma unroll
    for (int mt = 0; mt < 4; mt++) {
        float s0 = 0.0f, s1 = 0.0f;
#pragma unroll
        for (int nt = 0; nt < 4; nt++) {
            s0 += acc[mt][nt][0] * acc[mt][nt][0] + acc[mt][nt][1] * acc[mt][nt][1];
            s1 += acc[mt][nt][2] * acc[mt][nt][2] + acc[mt][nt][3] * acc[mt][nt][3];
        }
        s0 += __shfl_xor_sync(0xffffffffu, s0, 1);
        s0 += __shfl_xor_sync(0xffffffffu, s0, 2);
        s1 += __shfl_xor_sync(0xffffffffu, s1, 1);
        s1 += __shfl_xor_sync(0xffffffffu, s1, 2);
        ssa[mt] = s0;
        ssb[mt] = s1;
    }

    CP_WAIT0();
    __syncthreads();   // cp.async stages drained; smem free for reuse

    // 2) cross-warp reduce via smem: ssbuf[row][warp-col-group]
    float* ssbuf = (float*)(dsm + 34816);
    const int wq4 = wid & 3;
    if ((lane & 3) == 0) {
#pragma unroll
        for (int mt = 0; mt < 4; mt++) {
            const int r0 = wm + mt * 16 + (lane >> 2);
            ssbuf[r0 * 4 + wq4] = ssa[mt];
            ssbuf[(r0 + 8) * 4 + wq4] = ssb[mt];
        }
    }
    __syncthreads();

    // 3) normalize (+qscale for q), stage fp16 into smem (stride 264 B)
    const float qsc = (seg == 0) ? 0.1275174985f : 1.0f;   // 1/sqrt(128)*log2(e)
    float wv[8];
#pragma unroll
    for (int nt = 0; nt < 4; nt++) {
        const int c = wn + nt * 8 + (lane & 3) * 2;
        wv[2 * nt]     = w[c];
        wv[2 * nt + 1] = w[c + 1];
    }
#pragma unroll
    for (int mt = 0; mt < 4; mt++) {
        const int r0 = wm + mt * 16 + (lane >> 2);
        const int r1 = r0 + 8;
        const float sr0 = ssbuf[r0 * 4] + ssbuf[r0 * 4 + 1] +
                          ssbuf[r0 * 4 + 2] + ssbuf[r0 * 4 + 3];
        const float sr1 = ssbuf[r1 * 4] + ssbuf[r1 * 4 + 1] +
                          ssbuf[r1 * 4 + 2] + ssbuf[r1 * 4 + 3];
        const float rm0 = rsqrtf(sr0 * (1.0f / 128.0f) + 1e-6f) * qsc;
        const float rm1 = rsqrtf(sr1 * (1.0f / 128.0f) + 1e-6f) * qsc;
#pragma unroll
        for (int nt = 0; nt < 4; nt++) {
            const int c = wn + nt * 8 + (lane & 3) * 2;
            acc[mt][nt][0] *= rm0 * wv[2 * nt];
            acc[mt][nt][1] *= rm0 * wv[2 * nt + 1];
            acc[mt][nt][2] *= rm1 * wv[2 * nt];
            acc[mt][nt][3] *= rm1 * wv[2 * nt + 1];
            *(uint32_t*)(dsm + r0 * 264 + c * 2) =
                cvt2h(acc[mt][nt][0], acc[mt][nt][1]);
            *(uint32_t*)(dsm + r1 * 264 + c * 2) =
                cvt2h(acc[mt][nt][2], acc[mt][nt][3]);
        }
    }
    __syncthreads();

    // 4) RoPE (partner col = c ^ 64; sign warp-uniform) + strided fp16 store
    const float sgn = (wn < 64) ? -1.0f : 1.0f;
#pragma unroll
    for (int mt = 0; mt < 4; mt++) {
        const int r0 = wm + mt * 16 + (lane >> 2);
        const int s0 = sbase_row + r0;
        const int s1 = s0 + 8;
        const size_t o0 = ((size_t)(bb * S_ + s0) * nheads + h) * HD_;
        const size_t o1 = ((size_t)(bb * S_ + s1) * nheads + h) * HD_;
#pragma unroll
        for (int nt = 0; nt < 4; nt++) {
            const int c  = wn + nt * 8 + (lane & 3) * 2;
            const int fi = c & 63;
            const int pc = c ^ 64;
            const float c00 = ctab[s0 * 64 + fi];
            const float c01 = ctab[s0 * 64 + fi + 1];
            const float sn00 = stab[s0 * 64 + fi];
            const float sn01 = stab[s0 * 64 + fi + 1];
            const float c10 = ctab[s1 * 64 + fi];
            const float c11 = ctab[s1 * 64 + fi + 1];
            const float sn10 = stab[s1 * 64 + fi];
            const float sn11 = stab[s1 * 64 + fi + 1];
            __half2 p0 = *(__half2*)(dsm + r0 * 264 + pc * 2);
            __half2 p1 = *(__half2*)(dsm + (r0 + 8) * 264 + pc * 2);
            float2 pf0 = __half22float2(p0);
            float2 pf1 = __half22float2(p1);
            const float out00 = acc[mt][nt][0] * c00 + sgn * pf0.x * sn00;
            const float out01 = acc[mt][nt][1] * c01 + sgn * pf0.y * sn01;
            const float out10 = acc[mt][nt][2] * c10 + sgn * pf1.x * sn10;
            const float out11 = acc[mt][nt][3] * c11 + sgn * pf1.y * sn11;
            *(uint32_t*)&outp[o0 + c] = cvt2h(out00, out01);
            *(uint32_t*)&outp[o1 + c] = cvt2h(out10, out11);
        }
    }
}

// ============================================================================
// Wo projection (1-term; standard fp32 epilogue) — unchanged math.
// ============================================================================
__global__ __launch_bounds__(256, 2)
void wo_gemm_kernel(const __half* __restrict__ Ah,
                    const __half* __restrict__ Bh,
                    float* __restrict__ C) {
    extern __shared__ __align__(16) char dsm[];
    const uint32_t sbase = smem_u32(dsm);

    const int tid  = threadIdx.x;
    const int lane = tid & 31;
    const int wid  = tid >> 5;
    const int wm = (wid >> 2) * 64;
    const int wn = (wid & 3) * 32;
    const int m0 = blockIdx.y * 128;
    const int n0 = blockIdx.x * 128;

    float acc[4][4][4];
#pragma unroll
    for (int i = 0; i < 4; i++)
#pragma unroll
        for (int j = 0; j < 4; j++)
#pragma unroll
            for (int r = 0; r < 4; r++) acc[i][j][r] = 0.0f;

    const int a_row = tid >> 1;
    const int a_off = (tid & 1) * 16;
    const int b_kr  = tid >> 3;
    const int b_off = (tid & 7) * 16;

    GEMM_MAINLOOP(Ah, Bh, m0, n0, 1024, 2048, sbase);

#pragma unroll
    for (int mt = 0; mt < 4; mt++)
#pragma unroll
        for (int nt = 0; nt < 4; nt++) {
            int row = m0 + wm + mt * 16 + (lane >> 2);
            int col = n0 + wn + nt * 8 + (lane & 3) * 2;
            *(float2*)&C[(size_t)row * 1024 + col] =
                make_float2(acc[mt][nt][0], acc[mt][nt][1]);
            *(float2*)&C[(size_t)(row + 8) * 1024 + col] =
                make_float2(acc[mt][nt][2], acc[mt][nt][3]);
        }
}

// ============================================================================
// RoPE cos/sin table
// ============================================================================
__global__ void rope_table_kernel(const int* __restrict__ pos,
                                  float* __restrict__ ctab,
                                  float* __restrict__ stab) {
    int idx = blockIdx.x * blockDim.x + threadIdx.x;
    if (idx >= S_ * 64) return;
    int s  = idx >> 6;
    int fi = idx & 63;
    float inv = (float)exp(-13.815510557964274 * (double)fi / 64.0);
    float ang = (float)pos[s] * inv;
    float c, sn;
    sincosf(ang, &sn, &c);
    ctab[idx] = c;
    stab[idx] = sn;
}

// ============================================================================
// Flash attention (unchanged R15 — proven). Fully hi-only fp16.
// SMEM: Qh@0 | K0@34816 V0@52224 | K1@69632 V1@87040 => 104448 B.
// ============================================================================
#define ASTRIDE 272

__global__ __launch_bounds__(256, 1)
void attn_mma_kernel(const __half* __restrict__ qh_g,
                     const __half* __restrict__ kh_g,
                     const __half* __restrict__ vh_g,
                     __half* __restrict__ oh) {
    extern __shared__ __align__(16) char asmem[];
    const uint32_t sb = smem_u32(asmem);
    const uint32_t Qh = sb;
    const uint32_t KV0 = sb + 34816u;

    const int tid = threadIdx.x;
    const int lane = tid & 31;
    const int wid = tid >> 5;
    const int bh = blockIdx.y;
    const int b  = bh >> 4;
    const int h  = bh & 15;
    const int hk = h >> 1;
    const int qt = gridDim.x - 1 - blockIdx.x;
    const int q0 = qt * 128;
    const int wr = wid * 16;

    const int nkt = 2 * (qt + 1);

    {
        const int r = tid >> 1;
        const int hf = (tid & 1) * 64;
        const __half* qph = qh_g + ((size_t)(b * S_ + q0 + r) * NH_ + h) * HD_ + hf;
        const uint32_t off = (uint32_t)(r * ASTRIDE + hf * 2);
#pragma unroll
        for (int j = 0; j < 8; j++)
            CP_ASYNC16(Qh + off + j * 16, qph + j * 8);
        const int kr = tid >> 2;
        const int qd = (tid & 3) * 32;
        const size_t gro = ((size_t)(b * S_ + kr) * NKV_ + hk) * HD_ + qd;
        const uint32_t koff = KV0 + (uint32_t)(kr * ASTRIDE + qd * 2);
#pragma unroll
        for (int j = 0; j < 4; j++) {
            CP_ASYNC16(koff + j * 16, kh_g + gro + j * 8);
            CP_ASYNC16(koff + 17408u + j * 16, vh_g + gro + j * 8);
        }
        CP_COMMIT();
    }

    float oa[16][4];
    float m_i[2], l_i[2];
#pragma unroll
    for (int nt = 0; nt < 16; nt++)
#pragma unroll
        for (int r = 0; r < 4; r++) oa[nt][r] = 0.0f;
    m_i[0] = m_i[1] = -1e30f;
    l_i[0] = l_i[1] = 0.0f;

    for (int kt = 0; kt < nkt; kt++) {
        __syncthreads();
        if (kt + 1 < nkt) {
            const int kr = tid >> 2;
            const int qd = (tid & 3) * 32;
            const size_t gro =
                ((size_t)(b * S_ + (kt + 1) * 64 + kr) * NKV_ + hk) * HD_ + qd;
            const uint32_t koff = KV0 + (uint32_t)(((kt + 1) & 1) * 34816) +
                                  (uint32_t)(kr * ASTRIDE + qd * 2);
#pragma unroll
            for (int j = 0; j < 4; j++) {
                CP_ASYNC16(koff + j * 16, kh_g + gro + j * 8);
                CP_ASYNC16(koff + 17408u + j * 16, vh_g + gro + j * 8);
            }
        }
        CP_COMMIT();
        CP_WAIT1();
        __syncthreads();

        const int k0 = kt * 64;
        const uint32_t Kst = KV0 + (uint32_t)((kt & 1) * 34816);
        const uint32_t Vst = Kst + 17408u;

        float sc[8][4];
#pragma unroll
        for (int nt = 0; nt < 8; nt++)
#pragma unroll
            for (int r = 0; r < 4; r++) sc[nt][r] = 0.0f;

#pragma unroll
        for (int kc = 0; kc < 8; kc++) {
            const uint32_t aoff =
                (uint32_t)((wr + (lane & 15)) * ASTRIDE +
                           (kc * 16 + ((lane >> 4) << 3)) * 2);
            uint32_t qh4[4];
            ldsm4(qh4, Qh + aoff);
            const uint32_t bbase =
                Kst + (uint32_t)((((lane >> 4) << 3) + (lane & 7)) * ASTRIDE +
                                 (kc * 16 + ((lane >> 3) & 1) * 8) * 2);
#pragma unroll
            for (int bg = 0; bg < 4; bg++) {
                const uint32_t boff = bbase + (uint32_t)(bg * 16 * ASTRIDE);
                uint32_t kh4[4];
                ldsm4(kh4, boff);
                mma16816h(sc[2 * bg], qh4, kh4[0], kh4[1]);
                mma16816h(sc[2 * bg + 1], qh4, kh4[2], kh4[3]);
            }
        }

        const int row0 = q0 + wr + (lane >> 2);
        const int row1 = row0 + 8;
        if (kt >= 2 * qt) {
#pragma unroll
            for (int nt = 0; nt < 8; nt++) {
                int cb = k0 + nt * 8 + (lane & 3) * 2;
                if (cb > row0) sc[nt][0] = -1e30f;
                if (cb + 1 > row0) sc[nt][1] = -1e30f;
                if (cb > row1) sc[nt][2] = -1e30f;
                if (cb + 1 > row1) sc[nt][3] = -1e30f;
            }
        }

        float mx0 = sc[0][0], mx1 = sc[0][2];
#pragma unroll
        for (int nt = 0; nt < 8; nt++) {
            mx0 = fmaxf(mx0, fmaxf(sc[nt][0], sc[nt][1]));
            mx1 = fmaxf(mx1, fmaxf(sc[nt][2], sc[nt][3]));
        }
        mx0 = fmaxf(mx0, __shfl_xor_sync(0xffffffffu, mx0, 1));
        mx0 = fmaxf(mx0, __shfl_xor_sync(0xffffffffu, mx0, 2));
        mx1 = fmaxf(mx1, __shfl_xor_sync(0xffffffffu, mx1, 1));
        mx1 = fmaxf(mx1, __shfl_xor_sync(0xffffffffu, mx1, 2));
        const float mn0 = fmaxf(m_i[0], mx0);
        const float mn1 = fmaxf(m_i[1], mx1);
        const float alpha0 = exp2fast(m_i[0] - mn0);
        const float alpha1 = exp2fast(m_i[1] - mn1);
        m_i[0] = mn0;
        m_i[1] = mn1;

        float rs0 = 0.0f, rs1 = 0.0f;
#pragma unroll
        for (int nt = 0; nt < 8; nt++) {
            sc[nt][0] = exp2fast(sc[nt][0] - mn0);
            sc[nt][1] = exp2fast(sc[nt][1] - mn0);
            sc[nt][2] = exp2fast(sc[nt][2] - mn1);
            sc[nt][3] = exp2fast(sc[nt][3] - mn1);
            rs0 += sc[nt][0] + sc[nt][1];
            rs1 += sc[nt][2] + sc[nt][3];
        }
        rs0 += __shfl_xor_sync(0xffffffffu, rs0, 1);
        rs0 += __shfl_xor_sync(0xffffffffu, rs0, 2);
        rs1 += __shfl_xor_sync(0xffffffffu, rs1, 1);
        rs1 += __shfl_xor_sync(0xffffffffu, rs1, 2);
        l_i[0] = l_i[0] * alpha0 + rs0;
        l_i[1] = l_i[1] * alpha1 + rs1;
#pragma unroll
        for (int nt = 0; nt < 16; nt++) {
            oa[nt][0] *= alpha0;
            oa[nt][1] *= alpha0;
            oa[nt][2] *= alpha1;
            oa[nt][3] *= alpha1;
        }

#pragma unroll
        for (int kc = 0; kc < 4; kc++) {
            uint32_t ph[4];
            ph[0] = cvt2h(sc[2 * kc][0], sc[2 * kc][1]);
            ph[1] = cvt2h(sc[2 * kc][2], sc[2 * kc][3]);
            ph[2] = cvt2h(sc[2 * kc + 1][0], sc[2 * kc + 1][1]);
            ph[3] = cvt2h(sc[2 * kc + 1][2], sc[2 * kc + 1][3]);
            const uint32_t vbase =
                Vst + (uint32_t)((kc * 16 + (lane & 15)) * ASTRIDE +
                                 (((lane >> 4) << 3)) * 2);
#pragma unroll
            for (int dg = 0; dg < 8; dg++) {
                const uint32_t voff = vbase + (uint32_t)(dg * 32);
                uint32_t vh4[4];
                ldsm4t(vh4, voff);
                mma16816h(oa[2 * dg], ph, vh4[0], vh4[1]);
                mma16816h(oa[2 * dg + 1], ph, vh4[2], vh4[3]);
            }
        }
    }

    const float inv0 = 1.0f / l_i[0];
    const float inv1 = 1.0f / l_i[1];
    const int row0 = q0 + wr + (lane >> 2);
#pragma unroll
    for (int nt = 0; nt < 16; nt++) {
        const int d = nt * 8 + (lane & 3) * 2;
        const size_t i0 = (size_t)(b * S_ + row0) * 2048 + h * 128 + d;
        const size_t i1 = (size_t)(b * S_ + row0 + 8) * 2048 + h * 128 + d;
        *(uint32_t*)&oh[i0] = cvt2h(oa[nt][0] * inv0, oa[nt][1] * inv0);
        *(uint32_t*)&oh[i1] = cvt2h(oa[nt][2] * inv1, oa[nt][3] * inv1);
    }
}

// ============================================================================
// launch
// ============================================================================
extern "C" void kernel_launch(void* const* d_in, const int* in_sizes, int n_in,
                              void* d_out, int out_size) {
    const float* hidden = (const float*)d_in[0];
    const int*   pos    = (const int*)d_in[1];
    const float* Wq     = (const float*)d_in[2];
    const float* Wk     = (const float*)d_in[3];
    const float* Wv     = (const float*)d_in[4];
    const float* Wo     = (const float*)d_in[5];
    const float* qw     = (const float*)d_in[6];
    const float* kw     = (const float*)d_in[7];
    float* out = (float*)d_out;

    float *ct, *st;
    cudaGetSymbolAddress((void**)&ct, g_cos);
    cudaGetSymbolAddress((void**)&st, g_sin);

    __half *hidh, *wqh, *wkh, *wvh, *woh, *ath;
    __half *qh, *kh, *vh;
    cudaGetSymbolAddress((void**)&hidh, g_hid_h);
    cudaGetSymbolAddress((void**)&wqh,  g_wq_h);
    cudaGetSymbolAddress((void**)&wkh,  g_wk_h);
    cudaGetSymbolAddress((void**)&wvh,  g_wv_h);
    cudaGetSymbolAddress((void**)&woh,  g_wo_h);
    cudaGetSymbolAddress((void**)&ath,  g_at_h);
    cudaGetSymbolAddress((void**)&qh,   g_qh);
    cudaGetSymbolAddress((void**)&kh,   g_kh);
    cudaGetSymbolAddress((void**)&vh,   g_vh);

    // ---- conversions + RoPE table (independent; table needed by QKV epilogue)
    {
        int total = MROWS * 1024 / 8 + 2 * (1024 * 2048 / 8) +
                    2 * (1024 * 1024 / 8);            // 1310720
        convert_all_kernel<<<(total + 255) / 256, 256>>>(
            hidden, Wq, Wk, Wv, Wo, hidh, wqh, wkh, wvh, woh);
    }
    rope_table_kernel<<<(S_ * 64 + 255) / 256, 256>>>(pos, ct, st);

    const int gemm_smem = 3 * (int)STG_SZ;   // 56832
    cudaFuncSetAttribute(qkv_gemm_kernel,
                         cudaFuncAttributeMaxDynamicSharedMemorySize, gemm_smem);
    cudaFuncSetAttribute(wo_gemm_kernel,
                         cudaFuncAttributeMaxDynamicSharedMemorySize, gemm_smem);

    // fused QKV projection + RMSNorm + RoPE + fp16 store (one launch)
    qkv_gemm_kernel<<<dim3(4096 / 128, MROWS / 128), 256, gemm_smem>>>(
        hidh, wqh, wkh, wvh, qw, kw, ct, st, qh, kh, vh);

    // attention (fully hi-only; double-buffered K/V)
    {
        const int attn_smem = 104448;
        cudaFuncSetAttribute(attn_mma_kernel,
                             cudaFuncAttributeMaxDynamicSharedMemorySize,
                             attn_smem);
        attn_mma_kernel<<<dim3(S_ / 128, B_ * NH_), 256, attn_smem>>>(
            qh, kh, vh, ath);
    }

    // output projection (1-term fp16)
    wo_gemm_kernel<<<dim3(1024 / 128, MROWS / 128), 256, gemm_smem>>>(
        ath, woh, out);
}